// round 2
// baseline (speedup 1.0000x reference)
#include <cuda_runtime.h>
#include <math.h>
#include <float.h>

// ---------------- problem constants ----------------
static constexpr int NB = 8;       // batch
static constexpr int N1 = 4096;
static constexpr int N2 = 2048;
static constexpr int N3 = 512;
static constexpr int KNN = 32;

// ---------------- scratch (device globals; no allocations allowed) ----------
__device__ int   g_idx1[NB * N1 * KNN];
__device__ int   g_cnt1[NB * N1];
__device__ float g_x1  [NB * N1 * 64];
__device__ int   g_fi1 [NB * N2];
__device__ float g_pos2[NB * N2 * 3];
__device__ float g_x2g [NB * N2 * 64];
__device__ int   g_idx2[NB * N2 * KNN];
__device__ int   g_cnt2[NB * N2];
__device__ float g_x2  [NB * N2 * 128];
__device__ int   g_fi2 [NB * N3];
__device__ float g_pos3[NB * N3 * 3];
__device__ float g_x3g [NB * N3 * 128];
__device__ int   g_idx3[NB * N3 * KNN];
__device__ int   g_cnt3[NB * N3];
__device__ float g_x3  [NB * N3 * 256];

// ---------------- KNN: brute-force top-32 within radius ----------------
// grid (N/256, B), block 256. Per-thread sorted top-32 (ascending d2).
// Ties: strict '<' vs current worst and strict '>' while shifting keep the
// lower index, matching lax.top_k's lowest-index-first tie-break.
__global__ void knn_kernel(const float* __restrict__ pos, int N, float r2,
                           int* __restrict__ oidx, int* __restrict__ ocnt)
{
    __shared__ float4 sj[256];
    const int b = blockIdx.y;
    const int i = blockIdx.x * 256 + threadIdx.x;
    const float* pb = pos + (size_t)b * N * 3;

    const float xi = pb[i * 3 + 0], yi = pb[i * 3 + 1], zi = pb[i * 3 + 2];
    const float sqi = __fadd_rn(__fadd_rn(__fmul_rn(xi, xi), __fmul_rn(yi, yi)),
                                __fmul_rn(zi, zi));
    const float m2x = -2.f * xi, m2y = -2.f * yi, m2z = -2.f * zi;

    float bd[KNN];
    int   bi_[KNN];
#pragma unroll
    for (int k = 0; k < KNN; ++k) { bd[k] = FLT_MAX; bi_[k] = 0; }
    float worst = FLT_MAX;

    for (int t0 = 0; t0 < N; t0 += 256) {
        __syncthreads();
        {
            int j = t0 + threadIdx.x;
            float x = pb[j * 3 + 0], y = pb[j * 3 + 1], z = pb[j * 3 + 2];
            float sq = __fadd_rn(__fadd_rn(__fmul_rn(x, x), __fmul_rn(y, y)),
                                 __fmul_rn(z, z));
            sj[threadIdx.x] = make_float4(x, y, z, sq);
        }
        __syncthreads();
#pragma unroll 4
        for (int jj = 0; jj < 256; ++jj) {
            float4 q = sj[jj];
            float d2 = sqi + fmaf(m2x, q.x, fmaf(m2y, q.y, fmaf(m2z, q.z, q.w)));
            int j = t0 + jj;
            if (d2 < worst && j != i) {
                int p = KNN - 1;
                while (p > 0 && bd[p - 1] > d2) {
                    bd[p] = bd[p - 1]; bi_[p] = bi_[p - 1]; --p;
                }
                bd[p] = d2; bi_[p] = j;
                worst = bd[KNN - 1];
            }
        }
    }
    int cnt = 0;
    while (cnt < KNN && bd[cnt] <= r2) ++cnt;
    const int base = (b * N + i) * KNN;
    ocnt[b * N + i] = cnt;
#pragma unroll
    for (int k = 0; k < KNN; ++k) oidx[base + k] = bi_[k];
}

// ---------------- FPS: one block per batch element ----------------
// N = P*512 points. mind + positions register-resident (strided ownership).
// Argmax tie-break = smallest index (matches jnp.argmax first-occurrence).
template <int P>
__global__ void fps_kernel(const float* __restrict__ pos, int nS,
                           int* __restrict__ out)
{
    const int N = P * 512;
    const int b = blockIdx.x, t = threadIdx.x;
    const float* pb = pos + (size_t)b * N * 3;

    float px[P], py[P], pz[P], mind[P];
    const float x0 = pb[0], y0 = pb[1], z0 = pb[2];
#pragma unroll
    for (int p = 0; p < P; ++p) {
        int i = t + p * 512;
        px[p] = pb[i * 3 + 0]; py[p] = pb[i * 3 + 1]; pz[p] = pb[i * 3 + 2];
        float dx = px[p] - x0, dy = py[p] - y0, dz = pz[p] - z0;
        mind[p] = __fadd_rn(__fadd_rn(__fmul_rn(dx, dx), __fmul_rn(dy, dy)),
                            __fmul_rn(dz, dz));
    }
    if (t == 0) out[b * nS + 0] = 0;

    __shared__ float sv[16];
    __shared__ int   si[16];
    __shared__ float scur[3];
    __shared__ int   sgi;

    for (int s = 1; s < nS; ++s) {
        float bv = -1.f; int bidx = 0x7fffffff;
#pragma unroll
        for (int p = 0; p < P; ++p)
            if (mind[p] > bv) { bv = mind[p]; bidx = t + p * 512; }
#pragma unroll
        for (int off = 16; off > 0; off >>= 1) {
            float ov = __shfl_down_sync(0xffffffffu, bv, off);
            int   oi = __shfl_down_sync(0xffffffffu, bidx, off);
            if (ov > bv || (ov == bv && oi < bidx)) { bv = ov; bidx = oi; }
        }
        if ((t & 31) == 0) { sv[t >> 5] = bv; si[t >> 5] = bidx; }
        __syncthreads();
        if (t < 32) {
            bv   = (t < 16) ? sv[t] : -FLT_MAX;
            bidx = (t < 16) ? si[t] : 0x7fffffff;
#pragma unroll
            for (int off = 16; off > 0; off >>= 1) {
                float ov = __shfl_down_sync(0xffffffffu, bv, off);
                int   oi = __shfl_down_sync(0xffffffffu, bidx, off);
                if (ov > bv || (ov == bv && oi < bidx)) { bv = ov; bidx = oi; }
            }
            if (t == 0) {
                sgi = bidx;
                out[b * nS + s] = bidx;
                scur[0] = pb[bidx * 3 + 0];
                scur[1] = pb[bidx * 3 + 1];
                scur[2] = pb[bidx * 3 + 2];
            }
        }
        __syncthreads();
        const float cx = scur[0], cy = scur[1], cz = scur[2];
        (void)sgi;
#pragma unroll
        for (int p = 0; p < P; ++p) {
            float dx = px[p] - cx, dy = py[p] - cy, dz = pz[p] - cz;
            float d = __fadd_rn(__fadd_rn(__fmul_rn(dx, dx), __fmul_rn(dy, dy)),
                                __fmul_rn(dz, dz));
            mind[p] = fminf(mind[p], d);
        }
        __syncthreads();
    }
}

// ---------------- gather after FPS ----------------
__global__ void gather_kernel(const float* __restrict__ xin,
                              const float* __restrict__ posin,
                              const int* __restrict__ fi,
                              float* __restrict__ xo, float* __restrict__ poso,
                              int Nin, int Nout, int C)
{
    const int tid = blockIdx.x * blockDim.x + threadIdx.x;
    const int stride = gridDim.x * blockDim.x;
    const int totX = NB * Nout * C;
    for (int e = tid; e < totX; e += stride) {
        int c = e % C, m = (e / C) % Nout, b = e / (C * Nout);
        int j = fi[b * Nout + m];
        xo[e] = xin[((size_t)b * Nin + j) * C + c];
    }
    const int totP = NB * Nout * 3;
    for (int e = tid; e < totP; e += stride) {
        int d = e % 3, m = (e / 3) % Nout, b = e / (3 * Nout);
        int j = fi[b * Nout + m];
        poso[e] = posin[((size_t)b * Nin + j) * 3 + d];
    }
}

// ---------------- PointNetConv: per-point dual mini-GEMM + masked max ------
// block = COUT threads, one point per block. Register tile 4 cols x 8 k.
template <int CINX, int CHID, int COUT>
__global__ void __launch_bounds__(COUT)
conv_kernel(const float* __restrict__ xin, const float* __restrict__ pos,
            const int* __restrict__ kidx, const int* __restrict__ kcnt,
            const float* __restrict__ W1, const float* __restrict__ b1,
            const float* __restrict__ W2, const float* __restrict__ b2,
            float* __restrict__ xout, int N)
{
    constexpr int CINF = CINX + 3;
    extern __shared__ float smem[];
    float* sfeat = smem;               // [32][CINF]
    float* sh1   = smem + 32 * CINF;   // [32][CHID]
    __shared__ int   sidx[KNN];
    __shared__ float spi[3];
    __shared__ int   scnt;

    const int b = blockIdx.y, i = blockIdx.x, t = threadIdx.x;

    if (t < KNN) sidx[t] = kidx[((size_t)b * N + i) * KNN + t];
    if (t == 0)  scnt = kcnt[b * N + i];
    if (t < 3)   spi[t] = pos[((size_t)b * N + i) * 3 + t];
    for (int e = t; e < 32 * CINF; e += COUT) sfeat[e] = 0.f;
    __syncthreads();
    const int cnt = scnt;

    for (int e = t; e < cnt * CINF; e += COUT) {
        int k = e / CINF, f = e - k * CINF;
        int j = sidx[k];
        float v;
        if (f < CINX) v = xin[((size_t)b * N + j) * CINX + f];
        else          v = pos[((size_t)b * N + j) * 3 + (f - CINX)] - spi[f - CINX];
        sfeat[e] = v;
    }
    __syncthreads();

    // phase 1: h1 = relu(feats @ W1 + b1)   [32 x CINF] @ [CINF x CHID]
    {
        constexpr int CG = CHID / 4;
        const int c0 = (t % CG) * 4;
        const int k0 = (t / CG) * 8;
        float h[4][8];
        float4 bb = *(const float4*)&b1[c0];
#pragma unroll
        for (int k = 0; k < 8; ++k) {
            h[0][k] = bb.x; h[1][k] = bb.y; h[2][k] = bb.z; h[3][k] = bb.w;
        }
#pragma unroll 2
        for (int f = 0; f < CINF; ++f) {
            float4 w = *(const float4*)&W1[f * CHID + c0];
#pragma unroll
            for (int k = 0; k < 8; ++k) {
                float s = sfeat[(k0 + k) * CINF + f];
                h[0][k] = fmaf(s, w.x, h[0][k]);
                h[1][k] = fmaf(s, w.y, h[1][k]);
                h[2][k] = fmaf(s, w.z, h[2][k]);
                h[3][k] = fmaf(s, w.w, h[3][k]);
            }
        }
#pragma unroll
        for (int k = 0; k < 8; ++k) {
            float4 v;
            v.x = fmaxf(h[0][k], 0.f); v.y = fmaxf(h[1][k], 0.f);
            v.z = fmaxf(h[2][k], 0.f); v.w = fmaxf(h[3][k], 0.f);
            *(float4*)&sh1[(k0 + k) * CHID + c0] = v;
        }
    }
    __syncthreads();

    // phase 2: acc = h1 @ W2; masked max over valid k; +bias; outer relu
    float m0 = -FLT_MAX, m1 = -FLT_MAX, m2 = -FLT_MAX, m3 = -FLT_MAX;
    int o0, kg;
    {
        constexpr int OG = COUT / 4;
        o0 = (t % OG) * 4;
        kg = t / OG;
        const int k0 = kg * 8;
        float a[4][8];
#pragma unroll
        for (int k = 0; k < 8; ++k) {
            a[0][k] = 0.f; a[1][k] = 0.f; a[2][k] = 0.f; a[3][k] = 0.f;
        }
#pragma unroll 2
        for (int cc = 0; cc < CHID; ++cc) {
            float4 w = *(const float4*)&W2[cc * COUT + o0];
#pragma unroll
            for (int k = 0; k < 8; ++k) {
                float s = sh1[(k0 + k) * CHID + cc];
                a[0][k] = fmaf(s, w.x, a[0][k]);
                a[1][k] = fmaf(s, w.y, a[1][k]);
                a[2][k] = fmaf(s, w.z, a[2][k]);
                a[3][k] = fmaf(s, w.w, a[3][k]);
            }
        }
#pragma unroll
        for (int k = 0; k < 8; ++k) {
            if (k0 + k < cnt) {
                m0 = fmaxf(m0, a[0][k]); m1 = fmaxf(m1, a[1][k]);
                m2 = fmaxf(m2, a[2][k]); m3 = fmaxf(m3, a[3][k]);
            }
        }
    }
    __syncthreads();
    sh1[kg * COUT + o0 + 0] = m0;
    sh1[kg * COUT + o0 + 1] = m1;
    sh1[kg * COUT + o0 + 2] = m2;
    sh1[kg * COUT + o0 + 3] = m3;
    __syncthreads();
    float mm = fmaxf(fmaxf(sh1[t], sh1[COUT + t]),
                     fmaxf(sh1[2 * COUT + t], sh1[3 * COUT + t]));
    float r = (cnt > 0) ? fmaxf(mm + b2[t], 0.f) : 0.f;
    xout[((size_t)b * N + i) * COUT + t] = r;
}

// ---------------- head: global max pool + MLPs + log_softmax ----------------
__global__ void head_kernel(const float* __restrict__ x3,
                            const float* __restrict__ Wc1, const float* __restrict__ bc1,
                            const float* __restrict__ Wc2, const float* __restrict__ bc2,
                            const float* __restrict__ Wc3, const float* __restrict__ bc3,
                            const float* __restrict__ Wd1, const float* __restrict__ bd1,
                            const float* __restrict__ Wd2, const float* __restrict__ bd2,
                            float* __restrict__ out)
{
    __shared__ float sf[256], sh[256], sh2[256], slog[40], sd[2];
    const int b = blockIdx.x, t = threadIdx.x;

    float m = -FLT_MAX;
    for (int n = 0; n < N3; ++n)
        m = fmaxf(m, x3[((size_t)b * N3 + n) * 256 + t]);
    sf[t] = m;
    __syncthreads();

    float a = bc1[t];
    for (int c = 0; c < 256; ++c) a = fmaf(sf[c], Wc1[c * 256 + t], a);
    sh[t] = fmaxf(a, 0.f);
    __syncthreads();

    a = bc2[t];
    for (int c = 0; c < 256; ++c) a = fmaf(sh[c], Wc2[c * 256 + t], a);
    sh2[t] = fmaxf(a, 0.f);
    __syncthreads();

    if (t < 40) {
        float l = bc3[t];
        for (int c = 0; c < 256; ++c) l = fmaf(sh2[c], Wc3[c * 40 + t], l);
        slog[t] = l;
    }
    float a2 = bd1[t];
    for (int c = 0; c < 256; ++c) a2 = fmaf(sf[c], Wd1[c * 256 + t], a2);
    a2 = fmaxf(a2, 0.f);
    __syncthreads();
    sh[t] = a2;
    __syncthreads();
    if (t < 2) {
        float l = bd2[t];
        for (int c = 0; c < 256; ++c) l = fmaf(sh[c], Wd2[c * 2 + t], l);
        sd[t] = l;
    }
    __syncthreads();

    if (t < 40) {
        float mx = -FLT_MAX;
        for (int j = 0; j < 40; ++j) mx = fmaxf(mx, slog[j]);
        float se = 0.f;
        for (int j = 0; j < 40; ++j) se += expf(slog[j] - mx);
        out[b * 40 + t] = slog[t] - mx - logf(se);
    }
    if (t < 2) {
        float mx = fmaxf(sd[0], sd[1]);
        float se = expf(sd[0] - mx) + expf(sd[1] - mx);
        out[NB * 40 + b * 2 + t] = sd[t] - mx - logf(se);
    }
}

// ---------------- launch ----------------
extern "C" void kernel_launch(void* const* d_in, const int* in_sizes, int n_in,
                              void* d_out, int out_size)
{
    const float* pos = (const float*)d_in[0];
    const float* W1a = (const float*)d_in[1];  const float* b1a = (const float*)d_in[2];
    const float* W1b = (const float*)d_in[3];  const float* b1b = (const float*)d_in[4];
    const float* W2a = (const float*)d_in[5];  const float* b2a = (const float*)d_in[6];
    const float* W2b = (const float*)d_in[7];  const float* b2b = (const float*)d_in[8];
    const float* W3a = (const float*)d_in[9];  const float* b3a = (const float*)d_in[10];
    const float* W3b = (const float*)d_in[11]; const float* b3b = (const float*)d_in[12];
    const float* Wc1 = (const float*)d_in[13]; const float* bc1 = (const float*)d_in[14];
    const float* Wc2 = (const float*)d_in[15]; const float* bc2 = (const float*)d_in[16];
    const float* Wc3 = (const float*)d_in[17]; const float* bc3 = (const float*)d_in[18];
    const float* Wd1 = (const float*)d_in[19]; const float* bd1 = (const float*)d_in[20];
    const float* Wd2 = (const float*)d_in[21]; const float* bd2 = (const float*)d_in[22];
    float* out = (float*)d_out;

    void *p_idx1, *p_cnt1, *p_x1, *p_fi1, *p_pos2, *p_x2g, *p_idx2, *p_cnt2,
         *p_x2, *p_fi2, *p_pos3, *p_x3g, *p_idx3, *p_cnt3, *p_x3;
    cudaGetSymbolAddress(&p_idx1, g_idx1);
    cudaGetSymbolAddress(&p_cnt1, g_cnt1);
    cudaGetSymbolAddress(&p_x1,   g_x1);
    cudaGetSymbolAddress(&p_fi1,  g_fi1);
    cudaGetSymbolAddress(&p_pos2, g_pos2);
    cudaGetSymbolAddress(&p_x2g,  g_x2g);
    cudaGetSymbolAddress(&p_idx2, g_idx2);
    cudaGetSymbolAddress(&p_cnt2, g_cnt2);
    cudaGetSymbolAddress(&p_x2,   g_x2);
    cudaGetSymbolAddress(&p_fi2,  g_fi2);
    cudaGetSymbolAddress(&p_pos3, g_pos3);
    cudaGetSymbolAddress(&p_x3g,  g_x3g);
    cudaGetSymbolAddress(&p_idx3, g_idx3);
    cudaGetSymbolAddress(&p_cnt3, g_cnt3);
    cudaGetSymbolAddress(&p_x3,   g_x3);

    const int sh1b = (32 * 3   + 32 * 64)  * 4;
    const int sh2b = (32 * 67  + 32 * 128) * 4;
    const int sh3b = (32 * 131 + 32 * 256) * 4;   // 49536 B > 48KB -> opt-in
    cudaFuncSetAttribute(conv_kernel<128, 256, 256>,
                         cudaFuncAttributeMaxDynamicSharedMemorySize, 50176);

    const float r1 = 0.2f, r2 = 0.4f, r3 = 1.0f;

    // level 1
    knn_kernel<<<dim3(N1 / 256, NB), 256>>>(pos, N1, r1 * r1,
                                            (int*)p_idx1, (int*)p_cnt1);
    conv_kernel<0, 64, 64><<<dim3(N1, NB), 64, sh1b>>>(
        nullptr, pos, (int*)p_idx1, (int*)p_cnt1,
        W1a, b1a, W1b, b1b, (float*)p_x1, N1);
    fps_kernel<8><<<NB, 512>>>(pos, N2, (int*)p_fi1);
    gather_kernel<<<256, 256>>>((float*)p_x1, pos, (int*)p_fi1,
                                (float*)p_x2g, (float*)p_pos2, N1, N2, 64);

    // level 2
    knn_kernel<<<dim3(N2 / 256, NB), 256>>>((float*)p_pos2, N2, r2 * r2,
                                            (int*)p_idx2, (int*)p_cnt2);
    conv_kernel<64, 128, 128><<<dim3(N2, NB), 128, sh2b>>>(
        (float*)p_x2g, (float*)p_pos2, (int*)p_idx2, (int*)p_cnt2,
        W2a, b2a, W2b, b2b, (float*)p_x2, N2);
    fps_kernel<4><<<NB, 512>>>((float*)p_pos2, N3, (int*)p_fi2);
    gather_kernel<<<256, 256>>>((float*)p_x2, (float*)p_pos2, (int*)p_fi2,
                                (float*)p_x3g, (float*)p_pos3, N2, N3, 128);

    // level 3
    knn_kernel<<<dim3(N3 / 256, NB), 256>>>((float*)p_pos3, N3, r3 * r3,
                                            (int*)p_idx3, (int*)p_cnt3);
    conv_kernel<128, 256, 256><<<dim3(N3, NB), 256, sh3b>>>(
        (float*)p_x3g, (float*)p_pos3, (int*)p_idx3, (int*)p_cnt3,
        W3a, b3a, W3b, b3b, (float*)p_x3, N3);

    // head
    head_kernel<<<NB, 256>>>((float*)p_x3, Wc1, bc1, Wc2, bc2, Wc3, bc3,
                             Wd1, bd1, Wd2, bd2, out);

    (void)in_sizes; (void)n_in; (void)out_size;
}